// round 4
// baseline (speedup 1.0000x reference)
#include <cuda_runtime.h>
#include <cstdint>

// out[n, d] = x[n, d] * w[d];  N = DIM = 8192, fp32.
// Column-owning streaming kernel with 2-stage software pipeline:
// prefetch batch i+1 (4x LDG.128) while scaling+storing batch i (4x STG.128),
// keeping read and write streams concurrently active at the memory controller.

static constexpr int DIM   = 8192;
static constexpr int DIM4  = DIM / 4;              // 2048 float4 columns
static constexpr int THREADS = 256;
static constexpr int COLBLOCKS = DIM4 / THREADS;   // 8 column-blocks per row
static constexpr int ROWGROUPS = 256;
static constexpr int BATCH = 4;                    // float4s per pipeline stage

__global__ void __launch_bounds__(THREADS)
diag_scale_pipe_kernel(const float4* __restrict__ x,
                       const float4* __restrict__ w4,
                       float4* __restrict__ out,
                       int n_rows)
{
    const int cb = blockIdx.x & (COLBLOCKS - 1);
    const int rg = blockIdx.x >> 3;
    const int col4 = cb * THREADS + threadIdx.x;

    const float4 wv = __ldg(&w4[col4]);            // once; stays in registers

    const long long rstride = (long long)ROWGROUPS * DIM4;   // between handled rows
    const long long bstride = (long long)BATCH * rstride;    // between batches

    const float4* xp = x   + (long long)rg * DIM4 + col4;
    float4*       op = out + (long long)rg * DIM4 + col4;

    const int nbatches = n_rows / (ROWGROUPS * BATCH);        // 8 for N=8192

    // Prologue: load batch 0
    float4 cur[BATCH];
    #pragma unroll
    for (int u = 0; u < BATCH; ++u)
        cur[u] = xp[(long long)u * rstride];

    for (int b = 0; b < nbatches - 1; ++b) {
        // Prefetch next batch (independent LDGs issued before the stores)
        float4 nxt[BATCH];
        #pragma unroll
        for (int u = 0; u < BATCH; ++u)
            nxt[u] = xp[bstride + (long long)u * rstride];

        // Scale + store current batch while next loads are in flight
        #pragma unroll
        for (int u = 0; u < BATCH; ++u) {
            cur[u].x *= wv.x;
            cur[u].y *= wv.y;
            cur[u].z *= wv.z;
            cur[u].w *= wv.w;
            op[(long long)u * rstride] = cur[u];
        }

        #pragma unroll
        for (int u = 0; u < BATCH; ++u) cur[u] = nxt[u];
        xp += bstride;
        op += bstride;
    }

    // Epilogue: store last batch
    #pragma unroll
    for (int u = 0; u < BATCH; ++u) {
        cur[u].x *= wv.x;
        cur[u].y *= wv.y;
        cur[u].z *= wv.z;
        cur[u].w *= wv.w;
        op[(long long)u * rstride] = cur[u];
    }
}

// Generic fallback (correct for any shape).
__global__ void __launch_bounds__(256)
diag_scale_fallback(const float4* __restrict__ x,
                    const float4* __restrict__ w4,
                    float4* __restrict__ out,
                    long long n4, int dim4)
{
    long long i = (long long)blockIdx.x * blockDim.x + threadIdx.x;
    long long stride = (long long)gridDim.x * blockDim.x;
    for (; i < n4; i += stride) {
        float4 v = x[i];
        int col4 = (int)(i % dim4);
        float4 wv = __ldg(&w4[col4]);
        v.x *= wv.x; v.y *= wv.y; v.z *= wv.z; v.w *= wv.w;
        out[i] = v;
    }
}

extern "C" void kernel_launch(void* const* d_in, const int* in_sizes, int n_in,
                              void* d_out, int out_size)
{
    const float4* x  = (const float4*)d_in[0];
    const float4* w4 = (const float4*)d_in[1];
    float4* out = (float4*)d_out;

    long long n_elems = (long long)out_size;
    int dim = in_sizes[1];
    int n_rows = (int)(n_elems / dim);

    bool fast_ok = (dim == DIM) && (n_rows % (ROWGROUPS * BATCH) == 0)
                   && (n_rows / (ROWGROUPS * BATCH) >= 2);

    if (fast_ok) {
        int blocks = COLBLOCKS * ROWGROUPS;    // 2048 blocks
        diag_scale_pipe_kernel<<<blocks, THREADS>>>(x, w4, out, n_rows);
    } else {
        long long n4 = n_elems / 4;
        const int threads = 256;
        int blocks = 148 * 8 * 4;
        long long needed = (n4 + threads - 1) / threads;
        if ((long long)blocks > needed) blocks = (int)needed;
        diag_scale_fallback<<<blocks, threads>>>(x, w4, out, n4, dim / 4);
    }
}

// round 5
// speedup vs baseline: 1.0084x; 1.0084x over previous
#include <cuda_runtime.h>
#include <cstdint>

// out[n, d] = x[n, d] * w[d];  N = DIM = 8192, fp32.
// FINAL: column-owning streaming kernel (best measured: 76.7us kernel, 6.33TB/s).
// Ceiling analysis (R1-R4): 4 structurally different kernels all pin at
// 6.24-6.33 TB/s -> mixed 50/50 R/W HBM stream limit (~79% of 8TB/s spec).
// Each thread owns one float4-column; weight in registers; 8 front-batched
// LDG.128 then 8 STG.128 per iteration; evict-first policy both directions.

static constexpr int DIM   = 8192;
static constexpr int DIM4  = DIM / 4;              // 2048 float4 columns
static constexpr int THREADS = 256;
static constexpr int COLBLOCKS = DIM4 / THREADS;   // 8 column-blocks per row
static constexpr int ROWGROUPS = 256;
static constexpr int UNROLL = 8;

__global__ void __launch_bounds__(THREADS)
diag_scale_stream_kernel(const float4* __restrict__ x,
                         const float4* __restrict__ w4,
                         float4* __restrict__ out,
                         int n_rows)
{
    const int cb = blockIdx.x & (COLBLOCKS - 1);
    const int rg = blockIdx.x >> 3;
    const int col4 = cb * THREADS + threadIdx.x;

    const float4 wv = __ldg(&w4[col4]);            // once; stays in registers

    const long long rstride = (long long)ROWGROUPS * DIM4;   // elems between rows
    const float4* xp = x   + (long long)rg * DIM4 + col4;
    float4*       op = out + (long long)rg * DIM4 + col4;

    const int iters = n_rows / (ROWGROUPS * UNROLL);          // 4 for N=8192

    for (int it = 0; it < iters; ++it) {
        float4 v[UNROLL];
        #pragma unroll
        for (int u = 0; u < UNROLL; ++u)
            v[u] = __ldcs(xp + (long long)u * rstride);       // 8 reads in flight
        #pragma unroll
        for (int u = 0; u < UNROLL; ++u) {
            v[u].x *= wv.x;
            v[u].y *= wv.y;
            v[u].z *= wv.z;
            v[u].w *= wv.w;
            __stcs(op + (long long)u * rstride, v[u]);        // 8 writes
        }
        xp += (long long)UNROLL * rstride;
        op += (long long)UNROLL * rstride;
    }
}

// Generic fallback (correct for any shape).
__global__ void __launch_bounds__(256)
diag_scale_fallback(const float4* __restrict__ x,
                    const float4* __restrict__ w4,
                    float4* __restrict__ out,
                    long long n4, int dim4)
{
    long long i = (long long)blockIdx.x * blockDim.x + threadIdx.x;
    long long stride = (long long)gridDim.x * blockDim.x;
    for (; i < n4; i += stride) {
        float4 v = x[i];
        int col4 = (int)(i % dim4);
        float4 wv = __ldg(&w4[col4]);
        v.x *= wv.x; v.y *= wv.y; v.z *= wv.z; v.w *= wv.w;
        out[i] = v;
    }
}

extern "C" void kernel_launch(void* const* d_in, const int* in_sizes, int n_in,
                              void* d_out, int out_size)
{
    const float4* x  = (const float4*)d_in[0];
    const float4* w4 = (const float4*)d_in[1];
    float4* out = (float4*)d_out;

    long long n_elems = (long long)out_size;
    int dim = in_sizes[1];
    int n_rows = (int)(n_elems / dim);

    bool fast_ok = (dim == DIM) && (n_rows % (ROWGROUPS * UNROLL) == 0);

    if (fast_ok) {
        int blocks = COLBLOCKS * ROWGROUPS;    // 2048 blocks
        diag_scale_stream_kernel<<<blocks, THREADS>>>(x, w4, out, n_rows);
    } else {
        long long n4 = n_elems / 4;
        const int threads = 256;
        int blocks = 148 * 8 * 4;
        long long needed = (n4 + threads - 1) / threads;
        if ((long long)blocks > needed) blocks = (int)needed;
        diag_scale_fallback<<<blocks, threads>>>(x, w4, out, n4, dim / 4);
    }
}